// round 2
// baseline (speedup 1.0000x reference)
#include <cuda_runtime.h>
#include <cuda_bf16.h>

#define MAXN 50000
#define MAXE 800000
#define CCH  64
#define NGRAPH 128

typedef unsigned long long u64;

// Scratch (device globals; no runtime allocation allowed)
__device__ float g_h[MAXN * CCH];
__device__ float g_t[MAXN * CCH];
__device__ float g_pre[MAXN * CCH];
__device__ float g_EA[MAXN * 12];
__device__ int   g_deg[MAXN];
__device__ int   g_off[MAXN + 1];
__device__ int   g_cur[MAXN];
__device__ int   g_csr_src[MAXE];
__device__ int   g_csr_eid[MAXE];
__device__ float g_sums[NGRAPH];
__device__ float g_counts[NGRAPH];

__device__ __forceinline__ float lrelu(float a) {
    return a > 0.0f ? a : 0.01f * a;
}

// packed f32x2 FMA: d = a*b + d (lane-wise on two packed fp32)
__device__ __forceinline__ void fma2(u64& d, u64 a, u64 b) {
    asm("fma.rn.f32x2 %0, %1, %2, %0;" : "+l"(d) : "l"(a), "l"(b));
}
__device__ __forceinline__ u64 pack2(float a) {
    u64 r;
    unsigned int ai = __float_as_uint(a);
    asm("mov.b64 %0, {%1, %1};" : "=l"(r) : "r"(ai));
    return r;
}

// ---------------------------------------------------------------------------
// CSR build: histogram of dst, exclusive scan, fill (src + edge id per slot)
// ---------------------------------------------------------------------------
__global__ void k_hist(const int* __restrict__ ei, int* __restrict__ deg, int E) {
    int e = blockIdx.x * 256 + threadIdx.x;
    if (e < E) atomicAdd(&deg[ei[E + e]], 1);
}

__global__ void k_scan(const int* __restrict__ deg, int* __restrict__ off,
                       int* __restrict__ cur, int N) {
    __shared__ int sh[1024];
    int tid = threadIdx.x;
    int C = (N + 1023) >> 10;
    int b = tid * C;
    int e = min(b + C, N);
    int s = 0;
    for (int j = b; j < e; j++) s += deg[j];
    sh[tid] = s;
    __syncthreads();
    for (int d = 1; d < 1024; d <<= 1) {
        int v = (tid >= d) ? sh[tid - d] : 0;
        __syncthreads();
        sh[tid] += v;
        __syncthreads();
    }
    int run = (tid == 0) ? 0 : sh[tid - 1];
    for (int j = b; j < e; j++) {
        off[j] = run; cur[j] = run;
        run += deg[j];
    }
    if (tid == 1023) off[N] = sh[1023];
}

__global__ void k_fill(const int* __restrict__ ei, int* __restrict__ cur,
                       int* __restrict__ csr_src, int* __restrict__ csr_eid, int E) {
    int e = blockIdx.x * 256 + threadIdx.x;
    if (e >= E) return;
    int src = ei[e];
    int dst = ei[E + e];
    int pos = atomicAdd(&cur[dst], 1);
    csr_src[pos] = src;
    csr_eid[pos] = e;
}

// ---------------------------------------------------------------------------
// EA[n] = sum of edge_attr over incoming edges (pull). Warp per node.
// ---------------------------------------------------------------------------
__global__ void k_ea_pull(const int* __restrict__ off, const int* __restrict__ csr_eid,
                          const float* __restrict__ edge_attr, float* __restrict__ EA, int N) {
    int warp = (blockIdx.x * blockDim.x + threadIdx.x) >> 5;
    int lane = threadIdx.x & 31;
    if (warp >= N) return;
    int s = off[warp], e = off[warp + 1];
    float acc = 0.0f;
    for (int j = s; j < e; j += 32) {
        int m = min(32, e - j);
        int eidv = (j + lane < e) ? csr_eid[j + lane] : 0;
        for (int i = 0; i < m; i++) {
            int eid = __shfl_sync(0xffffffffu, eidv, i);
            if (lane < 12) acc += edge_attr[eid * 12 + lane];
        }
    }
    if (lane < 12) EA[warp * 12 + lane] = acc;
}

// ---------------------------------------------------------------------------
// Read-in: h = leaky_relu([state|action] @ W_in + b_in). Warp per node.
// ---------------------------------------------------------------------------
__global__ void k_readin(const float* __restrict__ state,
                         const float* __restrict__ action,
                         const float* __restrict__ W,
                         const float* __restrict__ b,
                         float* __restrict__ h, int N) {
    __shared__ float Ws[12 * 64];
    __shared__ float bs[64];
    int tid = threadIdx.x;
    for (int i = tid; i < 12 * 64; i += 256) Ws[i] = W[i];
    if (tid < 64) bs[tid] = b[tid];
    __syncthreads();
    int warp = tid >> 5, lane = tid & 31;
    int n = blockIdx.x * 8 + warp;
    if (n >= N) return;

    float x = 0.0f;
    if (lane < 8)       x = state[n * 8 + lane];
    else if (lane < 12) x = action[n * 4 + (lane - 8)];

    float a0 = bs[2 * lane], a1 = bs[2 * lane + 1];
    const float2* W2 = (const float2*)Ws;
#pragma unroll
    for (int k = 0; k < 12; k++) {
        float a = __shfl_sync(0xffffffffu, x, k);
        float2 w = W2[k * 32 + lane];
        a0 += a * w.x; a1 += a * w.y;
    }
    ((float2*)h)[n * 32 + lane] = make_float2(lrelu(a0), lrelu(a1));
}

// ---------------------------------------------------------------------------
// Fused per-node GEMMs for one layer:
//   t   = h @ W_nbr                         -> g_t
//   pre = h @ W_self + EA @ W_edge + b_conv -> g_pre
// 256 threads, 32 nodes/block. thread -> (node = tid>>3, group g = tid&7):
// g<4 computes 16 t-channels, g>=4 computes 16 pre-channels.
// Inner product uses packed fma.rn.f32x2 (weights read as ulonglong2 pairs).
// ---------------------------------------------------------------------------
__global__ void k_fused(const float* __restrict__ h, const float* __restrict__ EA,
                        const float* __restrict__ Wnbr, const float* __restrict__ Wself,
                        const float* __restrict__ Wedge, const float* __restrict__ bconv,
                        float* __restrict__ t, float* __restrict__ pre, int N) {
    __shared__ __align__(16) float Wn[64 * 64];
    __shared__ __align__(16) float Ws[64 * 64];
    __shared__ __align__(16) float We[12 * 64];
    __shared__ __align__(16) float bs[64];
    __shared__ float hs[32 * 65];
    __shared__ float eas[32 * 12];

    int tid = threadIdx.x;
    for (int i = tid; i < 1024; i += 256) ((float4*)Wn)[i] = ((const float4*)Wnbr)[i];
    for (int i = tid; i < 1024; i += 256) ((float4*)Ws)[i] = ((const float4*)Wself)[i];
    for (int i = tid; i < 192;  i += 256) ((float4*)We)[i] = ((const float4*)Wedge)[i];
    if (tid < 64) bs[tid] = bconv[tid];

    int base = blockIdx.x * 32;
    for (int i = tid; i < 2048; i += 256) {
        int gidx = base * 64 + i;
        float v = (gidx < N * 64) ? h[gidx] : 0.0f;
        hs[(i >> 6) * 65 + (i & 63)] = v;
    }
    for (int i = tid; i < 384; i += 256) {
        int gidx = base * 12 + i;
        eas[i] = (gidx < N * 12) ? EA[gidx] : 0.0f;
    }
    __syncthreads();

    int node = tid >> 3, g = tid & 7;
    int n = base + node;
    if (n >= N) return;
    bool isPre = g >= 4;
    int cbase = (g & 3) * 16;
    const float* W = isPre ? Ws : Wn;

    u64 acc[8];
    if (isPre) {
        const ulonglong2* b2 = (const ulonglong2*)(bs + cbase);
#pragma unroll
        for (int i = 0; i < 4; i++) { acc[2 * i] = b2[i].x; acc[2 * i + 1] = b2[i].y; }
    } else {
#pragma unroll
        for (int i = 0; i < 8; i++) acc[i] = 0ull;
    }

    const float* hrow = hs + node * 65;
#pragma unroll 16
    for (int k = 0; k < 64; k++) {
        u64 aa = pack2(hrow[k]);
        const ulonglong2* w2 = (const ulonglong2*)(W + k * 64 + cbase);
#pragma unroll
        for (int q = 0; q < 4; q++) {
            ulonglong2 wv = w2[q];
            fma2(acc[2 * q], aa, wv.x);
            fma2(acc[2 * q + 1], aa, wv.y);
        }
    }
    if (isPre) {
        const float* earow = eas + node * 12;
#pragma unroll
        for (int k = 0; k < 12; k++) {
            u64 aa = pack2(earow[k]);
            const ulonglong2* w2 = (const ulonglong2*)(We + k * 64 + cbase);
#pragma unroll
            for (int q = 0; q < 4; q++) {
                ulonglong2 wv = w2[q];
                fma2(acc[2 * q], aa, wv.x);
                fma2(acc[2 * q + 1], aa, wv.y);
            }
        }
    }

    float* out = isPre ? pre : t;
    ulonglong2* o2 = (ulonglong2*)(out + n * 64 + cbase);
#pragma unroll
    for (int q = 0; q < 4; q++) o2[q] = make_ulonglong2(acc[2 * q], acc[2 * q + 1]);
}

// ---------------------------------------------------------------------------
// Pull: s = pre[n] + sum_{j in in(n)} t[src_j];
//   FINAL=0: h[n] = lrelu(s)
//   FINAL=1: y = lrelu(s) . W_out + b_out, atomically into per-graph sums/counts
// Warp per node; lane owns channels (2*lane, 2*lane+1).
// ---------------------------------------------------------------------------
template<bool FINAL>
__global__ void k_pull(const int* __restrict__ off, const int* __restrict__ csr_src,
                       const float* __restrict__ t, const float* __restrict__ pre,
                       float* __restrict__ hout,
                       const int* __restrict__ batch, const float* __restrict__ Wout,
                       const float* __restrict__ bout,
                       float* __restrict__ sums, float* __restrict__ counts, int N) {
    int warp = (blockIdx.x * blockDim.x + threadIdx.x) >> 5;
    int lane = threadIdx.x & 31;
    if (warp >= N) return;
    int s = off[warp], e = off[warp + 1];
    const float2* t2 = (const float2*)t;
    float2 acc = ((const float2*)pre)[warp * 32 + lane];
    for (int j = s; j < e; j += 32) {
        int m = min(32, e - j);
        int srcv = (j + lane < e) ? csr_src[j + lane] : 0;
        for (int i = 0; i < m; i++) {
            int sc = __shfl_sync(0xffffffffu, srcv, i);
            float2 v = t2[sc * 32 + lane];
            acc.x += v.x; acc.y += v.y;
        }
    }
    float h0 = lrelu(acc.x), h1 = lrelu(acc.y);
    if (!FINAL) {
        ((float2*)hout)[warp * 32 + lane] = make_float2(h0, h1);
    } else {
        float p = h0 * __ldg(&Wout[2 * lane]) + h1 * __ldg(&Wout[2 * lane + 1]);
#pragma unroll
        for (int o = 16; o > 0; o >>= 1) p += __shfl_down_sync(0xffffffffu, p, o);
        if (lane == 0) {
            int b = batch[warp];
            atomicAdd(&sums[b], p + bout[0]);
            atomicAdd(&counts[b], 1.0f);
        }
    }
}

__global__ void k_final(const float* __restrict__ sums, const float* __restrict__ counts,
                        float* __restrict__ out, int G) {
    int i = blockIdx.x * 128 + threadIdx.x;
    if (i < G) out[i] = sums[i] / fmaxf(counts[i], 1.0f);
}

// ---------------------------------------------------------------------------
extern "C" void kernel_launch(void* const* d_in, const int* in_sizes, int n_in,
                              void* d_out, int out_size) {
    const float* state     = (const float*)d_in[0];
    const float* action    = (const float*)d_in[1];
    const int*   edge_idx  = (const int*)d_in[2];
    const float* edge_attr = (const float*)d_in[3];
    const int*   batch     = (const int*)d_in[4];
    const float* W_in      = (const float*)d_in[5];
    const float* b_in      = (const float*)d_in[6];
    const float* W_self    = (const float*)d_in[7];
    const float* W_nbr     = (const float*)d_in[8];
    const float* W_edge    = (const float*)d_in[9];
    const float* b_conv    = (const float*)d_in[10];
    const float* W_out     = (const float*)d_in[11];
    const float* b_out     = (const float*)d_in[12];
    float* out = (float*)d_out;

    const int N = in_sizes[0] / 8;
    const int E = in_sizes[3] / 12;
    const int G = out_size;

    float *h_p, *t_p, *pre_p, *ea_p, *sums_p, *counts_p;
    int *deg_p, *off_p, *cur_p, *csrs_p, *csre_p;
    cudaGetSymbolAddress((void**)&h_p,      g_h);
    cudaGetSymbolAddress((void**)&t_p,      g_t);
    cudaGetSymbolAddress((void**)&pre_p,    g_pre);
    cudaGetSymbolAddress((void**)&ea_p,     g_EA);
    cudaGetSymbolAddress((void**)&deg_p,    g_deg);
    cudaGetSymbolAddress((void**)&off_p,    g_off);
    cudaGetSymbolAddress((void**)&cur_p,    g_cur);
    cudaGetSymbolAddress((void**)&csrs_p,   g_csr_src);
    cudaGetSymbolAddress((void**)&csre_p,   g_csr_eid);
    cudaGetSymbolAddress((void**)&sums_p,   g_sums);
    cudaGetSymbolAddress((void**)&counts_p, g_counts);

    const int nodeBlocks = (N + 7) / 8;          // pulls/readin: 8 warps per block
    const int fusedBlocks = (N + 31) / 32;       // fused: 32 nodes per block
    const int edgeBlocks = (E + 255) / 256;

    cudaMemsetAsync(deg_p,    0, (size_t)N * sizeof(int), 0);
    cudaMemsetAsync(sums_p,   0, NGRAPH * sizeof(float), 0);
    cudaMemsetAsync(counts_p, 0, NGRAPH * sizeof(float), 0);

    // CSR build
    k_hist<<<edgeBlocks, 256>>>(edge_idx, deg_p, E);
    k_scan<<<1, 1024>>>(deg_p, off_p, cur_p, N);
    k_fill<<<edgeBlocks, 256>>>(edge_idx, cur_p, csrs_p, csre_p, E);

    // EA (once) + read-in
    k_ea_pull<<<nodeBlocks, 256>>>(off_p, csre_p, edge_attr, ea_p, N);
    k_readin<<<nodeBlocks, 256>>>(state, action, W_in, b_in, h_p, N);

    // Layer 0
    k_fused<<<fusedBlocks, 256>>>(h_p, ea_p, W_nbr, W_self, W_edge, b_conv, t_p, pre_p, N);
    k_pull<false><<<nodeBlocks, 256>>>(off_p, csrs_p, t_p, pre_p, h_p,
                                       nullptr, nullptr, nullptr, nullptr, nullptr, N);
    // Layer 1
    k_fused<<<fusedBlocks, 256>>>(h_p, ea_p, W_nbr + 4096, W_self + 4096,
                                  W_edge + 768, b_conv + 64, t_p, pre_p, N);
    k_pull<true><<<nodeBlocks, 256>>>(off_p, csrs_p, t_p, pre_p, nullptr,
                                      batch, W_out, b_out, sums_p, counts_p, N);

    k_final<<<(G + 127) / 128, 128>>>(sums_p, counts_p, out, G);
}

// round 3
// speedup vs baseline: 2.3889x; 2.3889x over previous
#include <cuda_runtime.h>
#include <cuda_bf16.h>

#define MAXN 50000
#define MAXE 800000
#define NGRAPH 128

typedef unsigned long long u64;

// Scratch (device globals; no runtime allocation allowed)
__device__ float g_t[MAXN * 64];
__device__ float g_pre[MAXN * 64];
__device__ float g_h[MAXN * 64];
__device__ float g_agg0[MAXN * 64];
__device__ float g_agg1[MAXN * 64];
__device__ float g_EA[MAXN * 12];
__device__ float g_sums[NGRAPH];
__device__ float g_counts[NGRAPH];

__device__ __forceinline__ float lrelu(float a) { return a > 0.0f ? a : 0.01f * a; }

__device__ __forceinline__ void fma2(u64& d, u64 a, u64 b) {
    asm("fma.rn.f32x2 %0, %1, %2, %0;" : "+l"(d) : "l"(a), "l"(b));
}
__device__ __forceinline__ u64 pack2(float a) {
    u64 r; unsigned int ai = __float_as_uint(a);
    asm("mov.b64 %0, {%1, %1};" : "=l"(r) : "r"(ai));
    return r;
}

__device__ __forceinline__ void red_add_v4(float* addr, float4 v) {
    asm volatile("red.global.add.v4.f32 [%0], {%1,%2,%3,%4};"
                 :: "l"(addr), "f"(v.x), "f"(v.y), "f"(v.z), "f"(v.w) : "memory");
}

// ---------------------------------------------------------------------------
// Read-in: h = leaky_relu([state|action] @ W_in + b_in). Warp per node.
// ---------------------------------------------------------------------------
__global__ void k_readin(const float* __restrict__ state,
                         const float* __restrict__ action,
                         const float* __restrict__ W,
                         const float* __restrict__ b,
                         float* __restrict__ h, int N) {
    __shared__ float Ws[12 * 64];
    __shared__ float bs[64];
    int tid = threadIdx.x;
    for (int i = tid; i < 12 * 64; i += 256) Ws[i] = W[i];
    if (tid < 64) bs[tid] = b[tid];
    __syncthreads();
    int warp = tid >> 5, lane = tid & 31;
    int n = blockIdx.x * 8 + warp;
    if (n >= N) return;

    float x = 0.0f;
    if (lane < 8)       x = state[n * 8 + lane];
    else if (lane < 12) x = action[n * 4 + (lane - 8)];

    float a0 = bs[2 * lane], a1 = bs[2 * lane + 1];
    const float2* W2 = (const float2*)Ws;
#pragma unroll
    for (int k = 0; k < 12; k++) {
        float a = __shfl_sync(0xffffffffu, x, k);
        float2 w = W2[k * 32 + lane];
        a0 += a * w.x; a1 += a * w.y;
    }
    ((float2*)h)[n * 32 + lane] = make_float2(lrelu(a0), lrelu(a1));
}

// ---------------------------------------------------------------------------
// EA = segment_sum(edge_attr, dst). One thread per (edge, quarter-row).
// ---------------------------------------------------------------------------
__global__ void k_ea(const int* __restrict__ ei, const float* __restrict__ edge_attr,
                     float* __restrict__ EA, int E) {
    int idx = blockIdx.x * 256 + threadIdx.x;
    if (idx >= E * 3) return;
    int e = idx / 3;
    int j = idx - e * 3;
    int dst = ei[E + e];
    float4 v = ((const float4*)edge_attr)[e * 3 + j];
    red_add_v4(EA + dst * 12 + j * 4, v);
}

// ---------------------------------------------------------------------------
// Edge scatter: agg[dst] += t[src], 16 threads per edge, red.v4 to L2.
// ---------------------------------------------------------------------------
__global__ void k_scatter(const int* __restrict__ ei, const float* __restrict__ t,
                          float* __restrict__ agg, int E) {
    int idx = blockIdx.x * 256 + threadIdx.x;
    if (idx >= E * 16) return;
    int e = idx >> 4;
    int g = idx & 15;
    int src = ei[e];
    int dst = ei[E + e];
    float4 v = ((const float4*)t)[src * 16 + g];
    red_add_v4(agg + dst * 64 + g * 4, v);
}

// ---------------------------------------------------------------------------
// Fused layer GEMM. Tile: 128 nodes x 128 outputs (64 t-ch | 64 pre-ch).
// X = FIRST ? h : lrelu(pre + agg)  (computed in the loader)
//   t   = X @ W_nbr
//   pre = X @ W_self + EA @ W_edge + b_conv
// 256 threads; thread (ty=tid/16, tx=tid%16) owns 8 nodes x 8 channels,
// accumulated as 4 packed f32x2 per node via fma.rn.f32x2.
// Dynamic smem: X[128][68] | Wcat[64][128] | EA[128][12] | We[12][64] | b[64]
// ---------------------------------------------------------------------------
#define OFF_X  0
#define OFF_W  8704
#define OFF_EA 16896
#define OFF_WE 18432
#define OFF_B  19200
#define SMEM_FLOATS 19264

template<bool FIRST>
__global__ void __launch_bounds__(256, 2)
k_gemm(const float* __restrict__ h,
       float* pre,                       // in (if !FIRST) and out (aliased; safe: block-exclusive rows, read fully before write)
       const float* __restrict__ agg,
       const float* __restrict__ EA,
       const float* __restrict__ Wn, const float* __restrict__ Wsf,
       const float* __restrict__ We, const float* __restrict__ bias,
       float* __restrict__ t, int N) {
    extern __shared__ float sm[];
    int tid = threadIdx.x;
    int base = blockIdx.x * 128;

    // ---- load X (with fused activation for layer>0) ----
    for (int j = tid; j < 2048; j += 256) {
        int node = j >> 4, kq = j & 15;
        int gn = base + node;
        float4 v = make_float4(0.f, 0.f, 0.f, 0.f);
        if (gn < N) {
            if (FIRST) {
                v = ((const float4*)h)[gn * 16 + kq];
            } else {
                float4 p = ((const float4*)pre)[gn * 16 + kq];
                float4 a = ((const float4*)agg)[gn * 16 + kq];
                v.x = lrelu(p.x + a.x); v.y = lrelu(p.y + a.y);
                v.z = lrelu(p.z + a.z); v.w = lrelu(p.w + a.w);
            }
        }
        *(float4*)&sm[OFF_X + node * 68 + kq * 4] = v;
    }
    // ---- load Wcat = [Wn | Wself] ----
    for (int j = tid; j < 2048; j += 256) {
        int k = j >> 5, c4 = j & 31;
        float4 wv = (c4 < 16) ? ((const float4*)Wn)[k * 16 + c4]
                              : ((const float4*)Wsf)[k * 16 + (c4 - 16)];
        *(float4*)&sm[OFF_W + k * 128 + c4 * 4] = wv;
    }
    // ---- load EA tile ----
    for (int j = tid; j < 1536; j += 256) {
        int node = j / 12, q = j - node * 12;
        int gn = base + node;
        sm[OFF_EA + node * 12 + q] = (gn < N) ? EA[gn * 12 + q] : 0.0f;
    }
    for (int j = tid; j < 768; j += 256) sm[OFF_WE + j] = We[j];
    if (tid < 64) sm[OFF_B + tid] = bias[tid];
    __syncthreads();

    int ty = tid >> 4;          // node group 0..15
    int tx = tid & 15;          // channel group 0..15
    bool isPre = tx >= 8;
    int cb = (tx & 7) * 8;      // channel base within the 64-wide half

    u64 acc[8][4];
    if (isPre) {
        const u64* b2 = (const u64*)&sm[OFF_B + cb];
#pragma unroll
        for (int n = 0; n < 8; n++) {
            acc[n][0] = b2[0]; acc[n][1] = b2[1];
            acc[n][2] = b2[2]; acc[n][3] = b2[3];
        }
    } else {
#pragma unroll
        for (int n = 0; n < 8; n++)
#pragma unroll
            for (int q = 0; q < 4; q++) acc[n][q] = 0ull;
    }

    const float* xrow  = &sm[OFF_X + ty * 8 * 68];
    const float* wbase = &sm[OFF_W + (isPre ? 64 : 0) + cb];

#pragma unroll 4
    for (int k = 0; k < 64; k++) {
        const ulonglong2* w2 = (const ulonglong2*)(wbase + k * 128);
        ulonglong2 wa = w2[0], wb = w2[1];
#pragma unroll
        for (int n = 0; n < 8; n++) {
            u64 a = pack2(xrow[n * 68 + k]);
            fma2(acc[n][0], a, wa.x); fma2(acc[n][1], a, wa.y);
            fma2(acc[n][2], a, wb.x); fma2(acc[n][3], a, wb.y);
        }
    }
    if (isPre) {
        const float* earow  = &sm[OFF_EA + ty * 8 * 12];
        const float* webase = &sm[OFF_WE + cb];
#pragma unroll
        for (int k = 0; k < 12; k++) {
            const ulonglong2* w2 = (const ulonglong2*)(webase + k * 64);
            ulonglong2 wa = w2[0], wb = w2[1];
#pragma unroll
            for (int n = 0; n < 8; n++) {
                u64 a = pack2(earow[n * 12 + k]);
                fma2(acc[n][0], a, wa.x); fma2(acc[n][1], a, wa.y);
                fma2(acc[n][2], a, wb.x); fma2(acc[n][3], a, wb.y);
            }
        }
    }

    float* outp = isPre ? pre : t;
#pragma unroll
    for (int n = 0; n < 8; n++) {
        int gn = base + ty * 8 + n;
        if (gn < N) {
            ulonglong2* o = (ulonglong2*)(outp + gn * 64 + cb);
            o[0] = make_ulonglong2(acc[n][0], acc[n][1]);
            o[1] = make_ulonglong2(acc[n][2], acc[n][3]);
        }
    }
}

// ---------------------------------------------------------------------------
// Readout: hfin = lrelu(pre + agg); y = hfin . W_out + b_out;
// scatter-add into per-graph sums/counts. Warp per node.
// ---------------------------------------------------------------------------
__global__ void k_readout(const float* __restrict__ pre, const float* __restrict__ agg,
                          const float* __restrict__ Wout, const float* __restrict__ bout,
                          const int* __restrict__ batch,
                          float* __restrict__ sums, float* __restrict__ counts, int N) {
    __shared__ float Ws[64];
    if (threadIdx.x < 64) Ws[threadIdx.x] = Wout[threadIdx.x];
    __syncthreads();
    int warp = threadIdx.x >> 5, lane = threadIdx.x & 31;
    int n = blockIdx.x * 8 + warp;
    if (n >= N) return;
    float2 p2 = ((const float2*)pre)[n * 32 + lane];
    float2 a2 = ((const float2*)agg)[n * 32 + lane];
    float h0 = lrelu(p2.x + a2.x), h1 = lrelu(p2.y + a2.y);
    float p = h0 * Ws[2 * lane] + h1 * Ws[2 * lane + 1];
#pragma unroll
    for (int o = 16; o > 0; o >>= 1) p += __shfl_down_sync(0xffffffffu, p, o);
    if (lane == 0) {
        int b = batch[n];
        atomicAdd(&sums[b], p + bout[0]);
        atomicAdd(&counts[b], 1.0f);
    }
}

__global__ void k_final(const float* __restrict__ sums, const float* __restrict__ counts,
                        float* __restrict__ out, int G) {
    int i = blockIdx.x * 128 + threadIdx.x;
    if (i < G) out[i] = sums[i] / fmaxf(counts[i], 1.0f);
}

// ---------------------------------------------------------------------------
extern "C" void kernel_launch(void* const* d_in, const int* in_sizes, int n_in,
                              void* d_out, int out_size) {
    const float* state     = (const float*)d_in[0];
    const float* action    = (const float*)d_in[1];
    const int*   edge_idx  = (const int*)d_in[2];
    const float* edge_attr = (const float*)d_in[3];
    const int*   batch     = (const int*)d_in[4];
    const float* W_in      = (const float*)d_in[5];
    const float* b_in      = (const float*)d_in[6];
    const float* W_self    = (const float*)d_in[7];
    const float* W_nbr     = (const float*)d_in[8];
    const float* W_edge    = (const float*)d_in[9];
    const float* b_conv    = (const float*)d_in[10];
    const float* W_out     = (const float*)d_in[11];
    const float* b_out     = (const float*)d_in[12];
    float* out = (float*)d_out;

    const int N = in_sizes[0] / 8;
    const int E = in_sizes[3] / 12;
    const int G = out_size;

    float *h_p, *t_p, *pre_p, *agg0_p, *agg1_p, *ea_p, *sums_p, *counts_p;
    cudaGetSymbolAddress((void**)&h_p,      g_h);
    cudaGetSymbolAddress((void**)&t_p,      g_t);
    cudaGetSymbolAddress((void**)&pre_p,    g_pre);
    cudaGetSymbolAddress((void**)&agg0_p,   g_agg0);
    cudaGetSymbolAddress((void**)&agg1_p,   g_agg1);
    cudaGetSymbolAddress((void**)&ea_p,     g_EA);
    cudaGetSymbolAddress((void**)&sums_p,   g_sums);
    cudaGetSymbolAddress((void**)&counts_p, g_counts);

    const int smemBytes = SMEM_FLOATS * 4;
    cudaFuncSetAttribute(k_gemm<true>,  cudaFuncAttributeMaxDynamicSharedMemorySize, smemBytes);
    cudaFuncSetAttribute(k_gemm<false>, cudaFuncAttributeMaxDynamicSharedMemorySize, smemBytes);

    const int nodeBlocks  = (N + 7) / 8;
    const int gemmBlocks  = (N + 127) / 128;

    cudaMemsetAsync(ea_p,     0, (size_t)N * 12 * sizeof(float), 0);
    cudaMemsetAsync(agg0_p,   0, (size_t)N * 64 * sizeof(float), 0);
    cudaMemsetAsync(agg1_p,   0, (size_t)N * 64 * sizeof(float), 0);
    cudaMemsetAsync(sums_p,   0, NGRAPH * sizeof(float), 0);
    cudaMemsetAsync(counts_p, 0, NGRAPH * sizeof(float), 0);

    k_readin<<<nodeBlocks, 256>>>(state, action, W_in, b_in, h_p, N);
    k_ea<<<(E * 3 + 255) / 256, 256>>>(edge_idx, edge_attr, ea_p, E);

    // Layer 0
    k_gemm<true><<<gemmBlocks, 256, smemBytes>>>(h_p, pre_p, agg0_p, ea_p,
                                                 W_nbr, W_self, W_edge, b_conv, t_p, N);
    k_scatter<<<(E * 16 + 255) / 256, 256>>>(edge_idx, t_p, agg0_p, E);

    // Layer 1 (loader computes lrelu(pre+agg0))
    k_gemm<false><<<gemmBlocks, 256, smemBytes>>>(h_p, pre_p, agg0_p, ea_p,
                                                  W_nbr + 4096, W_self + 4096,
                                                  W_edge + 768, b_conv + 64, t_p, N);
    k_scatter<<<(E * 16 + 255) / 256, 256>>>(edge_idx, t_p, agg1_p, E);

    k_readout<<<nodeBlocks, 256>>>(pre_p, agg1_p, W_out, b_out, batch,
                                   sums_p, counts_p, N);
    k_final<<<(G + 127) / 128, 128>>>(sums_p, counts_p, out, G);
}

// round 4
// speedup vs baseline: 2.4118x; 1.0096x over previous
#include <cuda_runtime.h>
#include <cuda_bf16.h>

#define MAXN 50000
#define MAXE 800000
#define NGRAPH 128

typedef unsigned long long u64;

// Scratch (device globals; no runtime allocation allowed)
__device__ float g_h[MAXN * 64];
__device__ float g_t[MAXN * 64];
__device__ float g_pre[MAXN * 64];
__device__ float g_EA[MAXN * 12];
__device__ int   g_deg[MAXN];
__device__ int   g_off[MAXN + 1];
__device__ int   g_cur[MAXN];
__device__ int   g_csr[MAXE];
__device__ float g_sc[2 * NGRAPH];   // [0..127]=sums, [128..255]=counts

__device__ __forceinline__ float lrelu(float a) { return a > 0.0f ? a : 0.01f * a; }

__device__ __forceinline__ void fma2(u64& d, u64 a, u64 b) {
    asm("fma.rn.f32x2 %0, %1, %2, %0;" : "+l"(d) : "l"(a), "l"(b));
}
__device__ __forceinline__ u64 pack2(float a) {
    u64 r; unsigned int ai = __float_as_uint(a);
    asm("mov.b64 %0, {%1, %1};" : "=l"(r) : "r"(ai));
    return r;
}
__device__ __forceinline__ void red_add_v4(float* addr, float4 v) {
    asm volatile("red.global.add.v4.f32 [%0], {%1,%2,%3,%4};"
                 :: "l"(addr), "f"(v.x), "f"(v.y), "f"(v.z), "f"(v.w) : "memory");
}

// ---------------------------------------------------------------------------
// CSR build over dst: histogram, 1-block scan, fill (src only)
// ---------------------------------------------------------------------------
__global__ void k_hist(const int* __restrict__ ei, int* __restrict__ deg, int E) {
    int e = blockIdx.x * 256 + threadIdx.x;
    if (e < E) atomicAdd(&deg[ei[E + e]], 1);
}

__global__ void k_scan(const int* __restrict__ deg, int* __restrict__ off,
                       int* __restrict__ cur, int N) {
    __shared__ int sh[1024];
    int tid = threadIdx.x;
    int C = (N + 1023) >> 10;
    int b = tid * C;
    int e = min(b + C, N);
    int s = 0;
    for (int j = b; j < e; j++) s += deg[j];
    sh[tid] = s;
    __syncthreads();
    for (int d = 1; d < 1024; d <<= 1) {
        int v = (tid >= d) ? sh[tid - d] : 0;
        __syncthreads();
        sh[tid] += v;
        __syncthreads();
    }
    int run = (tid == 0) ? 0 : sh[tid - 1];
    for (int j = b; j < e; j++) {
        off[j] = run; cur[j] = run;
        run += deg[j];
    }
    if (tid == 1023) off[N] = sh[1023];
}

__global__ void k_fill(const int* __restrict__ ei, int* __restrict__ cur,
                       int* __restrict__ csr, int E) {
    int e = blockIdx.x * 256 + threadIdx.x;
    if (e >= E) return;
    int src = ei[e];
    int dst = ei[E + e];
    int pos = atomicAdd(&cur[dst], 1);
    csr[pos] = src;
}

// ---------------------------------------------------------------------------
// EA = segment_sum(edge_attr, dst): scatter red.v4 (cheap; 41 MB total)
// ---------------------------------------------------------------------------
__global__ void k_ea(const int* __restrict__ ei, const float* __restrict__ edge_attr,
                     float* __restrict__ EA, int E) {
    int idx = blockIdx.x * 256 + threadIdx.x;
    if (idx >= E * 3) return;
    int e = idx / 3;
    int j = idx - e * 3;
    int dst = ei[E + e];
    float4 v = ((const float4*)edge_attr)[e * 3 + j];
    red_add_v4(EA + dst * 12 + j * 4, v);
}

// ---------------------------------------------------------------------------
// Read-in: h = leaky_relu([state|action] @ W_in + b_in). Warp per node.
// ---------------------------------------------------------------------------
__global__ void k_readin(const float* __restrict__ state,
                         const float* __restrict__ action,
                         const float* __restrict__ W,
                         const float* __restrict__ b,
                         float* __restrict__ h, int N) {
    __shared__ float Ws[12 * 64];
    __shared__ float bs[64];
    int tid = threadIdx.x;
    for (int i = tid; i < 12 * 64; i += 256) Ws[i] = W[i];
    if (tid < 64) bs[tid] = b[tid];
    __syncthreads();
    int warp = tid >> 5, lane = tid & 31;
    int n = blockIdx.x * 8 + warp;
    if (n >= N) return;

    float x = 0.0f;
    if (lane < 8)       x = state[n * 8 + lane];
    else if (lane < 12) x = action[n * 4 + (lane - 8)];

    float a0 = bs[2 * lane], a1 = bs[2 * lane + 1];
    const float2* W2 = (const float2*)Ws;
#pragma unroll
    for (int k = 0; k < 12; k++) {
        float a = __shfl_sync(0xffffffffu, x, k);
        float2 w = W2[k * 32 + lane];
        a0 += a * w.x; a1 += a * w.y;
    }
    ((float2*)h)[n * 32 + lane] = make_float2(lrelu(a0), lrelu(a1));
}

// ---------------------------------------------------------------------------
// Fused layer GEMM. Tile: 128 nodes x 128 outputs (64 t-ch | 64 pre-ch).
//   t   = h @ W_nbr
//   pre = h @ W_self + EA @ W_edge + b_conv
// 256 threads; thread (ty,tx) owns 8 nodes x 8 channels via fma.rn.f32x2.
// ---------------------------------------------------------------------------
#define OFF_X  0
#define OFF_W  8704
#define OFF_EA 16896
#define OFF_WE 18432
#define OFF_B  19200
#define SMEM_FLOATS 19264

__global__ void __launch_bounds__(256, 2)
k_gemm(const float* __restrict__ h, const float* __restrict__ EA,
       const float* __restrict__ Wn, const float* __restrict__ Wsf,
       const float* __restrict__ We, const float* __restrict__ bias,
       float* __restrict__ t, float* __restrict__ pre, int N) {
    extern __shared__ float sm[];
    int tid = threadIdx.x;
    int base = blockIdx.x * 128;

    for (int j = tid; j < 2048; j += 256) {
        int node = j >> 4, kq = j & 15;
        int gn = base + node;
        float4 v = make_float4(0.f, 0.f, 0.f, 0.f);
        if (gn < N) v = ((const float4*)h)[gn * 16 + kq];
        *(float4*)&sm[OFF_X + node * 68 + kq * 4] = v;
    }
    for (int j = tid; j < 2048; j += 256) {
        int k = j >> 5, c4 = j & 31;
        float4 wv = (c4 < 16) ? ((const float4*)Wn)[k * 16 + c4]
                              : ((const float4*)Wsf)[k * 16 + (c4 - 16)];
        *(float4*)&sm[OFF_W + k * 128 + c4 * 4] = wv;
    }
    for (int j = tid; j < 1536; j += 256) {
        int node = j / 12, q = j - node * 12;
        int gn = base + node;
        sm[OFF_EA + node * 12 + q] = (gn < N) ? EA[gn * 12 + q] : 0.0f;
    }
    for (int j = tid; j < 768; j += 256) sm[OFF_WE + j] = We[j];
    if (tid < 64) sm[OFF_B + tid] = bias[tid];
    __syncthreads();

    int ty = tid >> 4;
    int tx = tid & 15;
    bool isPre = tx >= 8;
    int cb = (tx & 7) * 8;

    u64 acc[8][4];
    if (isPre) {
        const u64* b2 = (const u64*)&sm[OFF_B + cb];
#pragma unroll
        for (int n = 0; n < 8; n++) {
            acc[n][0] = b2[0]; acc[n][1] = b2[1];
            acc[n][2] = b2[2]; acc[n][3] = b2[3];
        }
    } else {
#pragma unroll
        for (int n = 0; n < 8; n++)
#pragma unroll
            for (int q = 0; q < 4; q++) acc[n][q] = 0ull;
    }

    const float* xrow  = &sm[OFF_X + ty * 8 * 68];
    const float* wbase = &sm[OFF_W + (isPre ? 64 : 0) + cb];

#pragma unroll 4
    for (int k = 0; k < 64; k++) {
        const ulonglong2* w2 = (const ulonglong2*)(wbase + k * 128);
        ulonglong2 wa = w2[0], wb = w2[1];
#pragma unroll
        for (int n = 0; n < 8; n++) {
            u64 a = pack2(xrow[n * 68 + k]);
            fma2(acc[n][0], a, wa.x); fma2(acc[n][1], a, wa.y);
            fma2(acc[n][2], a, wb.x); fma2(acc[n][3], a, wb.y);
        }
    }
    if (isPre) {
        const float* earow  = &sm[OFF_EA + ty * 8 * 12];
        const float* webase = &sm[OFF_WE + cb];
#pragma unroll
        for (int k = 0; k < 12; k++) {
            const ulonglong2* w2 = (const ulonglong2*)(webase + k * 64);
            ulonglong2 wa = w2[0], wb = w2[1];
#pragma unroll
            for (int n = 0; n < 8; n++) {
                u64 a = pack2(earow[n * 12 + k]);
                fma2(acc[n][0], a, wa.x); fma2(acc[n][1], a, wa.y);
                fma2(acc[n][2], a, wb.x); fma2(acc[n][3], a, wb.y);
            }
        }
    }

    float* outp = isPre ? pre : t;
#pragma unroll
    for (int n = 0; n < 8; n++) {
        int gn = base + ty * 8 + n;
        if (gn < N) {
            ulonglong2* o = (ulonglong2*)(outp + gn * 64 + cb);
            o[0] = make_ulonglong2(acc[n][0], acc[n][1]);
            o[1] = make_ulonglong2(acc[n][2], acc[n][3]);
        }
    }
}

// ---------------------------------------------------------------------------
// CSR pull with MLP=8 batching. Warp per node, lane owns 2 channels (float2).
//   s = pre[n] + sum_{src in in(n)} t[src]
//   FINAL=0: h[n] = lrelu(s)
//   FINAL=1: y = lrelu(s).W_out + b_out -> per-graph atomic sums/counts
// ---------------------------------------------------------------------------
template<bool FINAL>
__global__ void k_pull(const int* __restrict__ off, const int* __restrict__ csr,
                       const float* __restrict__ t, const float* __restrict__ pre,
                       float* __restrict__ hout, const int* __restrict__ batch,
                       const float* __restrict__ Wout, const float* __restrict__ bout,
                       float* __restrict__ sc, int N) {
    int warp = (blockIdx.x * blockDim.x + threadIdx.x) >> 5;
    int lane = threadIdx.x & 31;
    if (warp >= N) return;
    int s = off[warp], e = off[warp + 1];
    const float2* t2 = (const float2*)t;
    float2 a0 = ((const float2*)pre)[warp * 32 + lane];
    float ax = a0.x, ay = a0.y;

    for (int j = s; j < e; j += 32) {
        int cnt = min(32, e - j);
        int sv = (j + lane < e) ? csr[j + lane] : 0;
        int i = 0;
#pragma unroll 1
        for (; i + 8 <= cnt; i += 8) {
            int b0 = __shfl_sync(0xffffffffu, sv, i + 0);
            int b1 = __shfl_sync(0xffffffffu, sv, i + 1);
            int b2 = __shfl_sync(0xffffffffu, sv, i + 2);
            int b3 = __shfl_sync(0xffffffffu, sv, i + 3);
            int b4 = __shfl_sync(0xffffffffu, sv, i + 4);
            int b5 = __shfl_sync(0xffffffffu, sv, i + 5);
            int b6 = __shfl_sync(0xffffffffu, sv, i + 6);
            int b7 = __shfl_sync(0xffffffffu, sv, i + 7);
            float2 v0 = t2[b0 * 32 + lane];
            float2 v1 = t2[b1 * 32 + lane];
            float2 v2 = t2[b2 * 32 + lane];
            float2 v3 = t2[b3 * 32 + lane];
            float2 v4 = t2[b4 * 32 + lane];
            float2 v5 = t2[b5 * 32 + lane];
            float2 v6 = t2[b6 * 32 + lane];
            float2 v7 = t2[b7 * 32 + lane];
            ax += ((v0.x + v1.x) + (v2.x + v3.x)) + ((v4.x + v5.x) + (v6.x + v7.x));
            ay += ((v0.y + v1.y) + (v2.y + v3.y)) + ((v4.y + v5.y) + (v6.y + v7.y));
        }
#pragma unroll 1
        for (; i < cnt; i++) {
            int b = __shfl_sync(0xffffffffu, sv, i);
            float2 v = t2[b * 32 + lane];
            ax += v.x; ay += v.y;
        }
    }

    float h0 = lrelu(ax), h1 = lrelu(ay);
    if (!FINAL) {
        ((float2*)hout)[warp * 32 + lane] = make_float2(h0, h1);
    } else {
        float p = h0 * __ldg(&Wout[2 * lane]) + h1 * __ldg(&Wout[2 * lane + 1]);
#pragma unroll
        for (int o = 16; o > 0; o >>= 1) p += __shfl_down_sync(0xffffffffu, p, o);
        if (lane == 0) {
            int b = batch[warp];
            atomicAdd(&sc[b], p + bout[0]);
            atomicAdd(&sc[NGRAPH + b], 1.0f);
        }
    }
}

__global__ void k_final(const float* __restrict__ sc, float* __restrict__ out, int G) {
    int i = blockIdx.x * 128 + threadIdx.x;
    if (i < G) out[i] = sc[i] / fmaxf(sc[NGRAPH + i], 1.0f);
}

// ---------------------------------------------------------------------------
extern "C" void kernel_launch(void* const* d_in, const int* in_sizes, int n_in,
                              void* d_out, int out_size) {
    const float* state     = (const float*)d_in[0];
    const float* action    = (const float*)d_in[1];
    const int*   edge_idx  = (const int*)d_in[2];
    const float* edge_attr = (const float*)d_in[3];
    const int*   batch     = (const int*)d_in[4];
    const float* W_in      = (const float*)d_in[5];
    const float* b_in      = (const float*)d_in[6];
    const float* W_self    = (const float*)d_in[7];
    const float* W_nbr     = (const float*)d_in[8];
    const float* W_edge    = (const float*)d_in[9];
    const float* b_conv    = (const float*)d_in[10];
    const float* W_out     = (const float*)d_in[11];
    const float* b_out     = (const float*)d_in[12];
    float* out = (float*)d_out;

    const int N = in_sizes[0] / 8;
    const int E = in_sizes[3] / 12;
    const int G = out_size;

    float *h_p, *t_p, *pre_p, *ea_p, *sc_p;
    int *deg_p, *off_p, *cur_p, *csr_p;
    cudaGetSymbolAddress((void**)&h_p,   g_h);
    cudaGetSymbolAddress((void**)&t_p,   g_t);
    cudaGetSymbolAddress((void**)&pre_p, g_pre);
    cudaGetSymbolAddress((void**)&ea_p,  g_EA);
    cudaGetSymbolAddress((void**)&deg_p, g_deg);
    cudaGetSymbolAddress((void**)&off_p, g_off);
    cudaGetSymbolAddress((void**)&cur_p, g_cur);
    cudaGetSymbolAddress((void**)&csr_p, g_csr);
    cudaGetSymbolAddress((void**)&sc_p,  g_sc);

    const int smemBytes = SMEM_FLOATS * 4;
    cudaFuncSetAttribute(k_gemm, cudaFuncAttributeMaxDynamicSharedMemorySize, smemBytes);

    const int nodeBlocks = (N + 7) / 8;
    const int gemmBlocks = (N + 127) / 128;
    const int edgeBlocks = (E + 255) / 256;

    cudaMemsetAsync(deg_p, 0, (size_t)N * sizeof(int), 0);
    cudaMemsetAsync(ea_p,  0, (size_t)N * 12 * sizeof(float), 0);
    cudaMemsetAsync(sc_p,  0, 2 * NGRAPH * sizeof(float), 0);

    // CSR build (dst-indexed, src stored)
    k_hist<<<edgeBlocks, 256>>>(edge_idx, deg_p, E);
    k_scan<<<1, 1024>>>(deg_p, off_p, cur_p, N);
    k_fill<<<edgeBlocks, 256>>>(edge_idx, cur_p, csr_p, E);

    // EA (once) + read-in
    k_ea<<<(E * 3 + 255) / 256, 256>>>(edge_idx, edge_attr, ea_p, E);
    k_readin<<<nodeBlocks, 256>>>(state, action, W_in, b_in, h_p, N);

    // Layer 0
    k_gemm<<<gemmBlocks, 256, smemBytes>>>(h_p, ea_p, W_nbr, W_self, W_edge, b_conv,
                                           t_p, pre_p, N);
    k_pull<false><<<nodeBlocks, 256>>>(off_p, csr_p, t_p, pre_p, h_p,
                                       nullptr, nullptr, nullptr, nullptr, N);
    // Layer 1
    k_gemm<<<gemmBlocks, 256, smemBytes>>>(h_p, ea_p, W_nbr + 4096, W_self + 4096,
                                           W_edge + 768, b_conv + 64, t_p, pre_p, N);
    k_pull<true><<<nodeBlocks, 256>>>(off_p, csr_p, t_p, pre_p, nullptr,
                                      batch, W_out, b_out, sc_p, N);

    k_final<<<(G + 127) / 128, 128>>>(sc_p, out, G);
}

// round 5
// speedup vs baseline: 3.0556x; 1.2669x over previous
#include <cuda_runtime.h>
#include <cuda_bf16.h>

#define MAXN 50000
#define MAXE 800000
#define NGRAPH 128

typedef unsigned long long u64;

// Scratch (device globals; no runtime allocation allowed)
__device__ float g_h[MAXN * 64];
__device__ float g_t[MAXN * 64];
__device__ float g_pre[MAXN * 64];
__device__ float g_EA[MAXN * 12];
__device__ int   g_deg[MAXN];
__device__ int   g_off[MAXN + 1];
__device__ int   g_cur[MAXN];
__device__ int   g_csr[MAXE];
__device__ float g_sc[2 * NGRAPH];   // [0..127]=sums, [128..255]=counts

__device__ __forceinline__ float lrelu(float a) { return a > 0.0f ? a : 0.01f * a; }

__device__ __forceinline__ void fma2(u64& d, u64 a, u64 b) {
    asm("fma.rn.f32x2 %0, %1, %2, %0;" : "+l"(d) : "l"(a), "l"(b));
}
__device__ __forceinline__ u64 pack2(float a) {
    u64 r; unsigned int ai = __float_as_uint(a);
    asm("mov.b64 %0, {%1, %1};" : "=l"(r) : "r"(ai));
    return r;
}
__device__ __forceinline__ void red_add_v4(float* addr, float4 v) {
    asm volatile("red.global.add.v4.f32 [%0], {%1,%2,%3,%4};"
                 :: "l"(addr), "f"(v.x), "f"(v.y), "f"(v.z), "f"(v.w) : "memory");
}

// ---------------------------------------------------------------------------
// CSR build over dst: histogram, 1-block scan, fill (src only)
// ---------------------------------------------------------------------------
__global__ void k_hist(const int* __restrict__ ei, int* __restrict__ deg, int E) {
    int e = blockIdx.x * 256 + threadIdx.x;
    if (e < E) atomicAdd(&deg[ei[E + e]], 1);
}

__global__ void k_scan(const int* __restrict__ deg, int* __restrict__ off,
                       int* __restrict__ cur, int N) {
    __shared__ int sh[1024];
    int tid = threadIdx.x;
    int C = (N + 1023) >> 10;
    int b = tid * C;
    int e = min(b + C, N);
    int s = 0;
    for (int j = b; j < e; j++) s += deg[j];
    sh[tid] = s;
    __syncthreads();
    for (int d = 1; d < 1024; d <<= 1) {
        int v = (tid >= d) ? sh[tid - d] : 0;
        __syncthreads();
        sh[tid] += v;
        __syncthreads();
    }
    int run = (tid == 0) ? 0 : sh[tid - 1];
    for (int j = b; j < e; j++) {
        off[j] = run; cur[j] = run;
        run += deg[j];
    }
    if (tid == 1023) off[N] = sh[1023];
}

__global__ void k_fill(const int* __restrict__ ei, int* __restrict__ cur,
                       int* __restrict__ csr, int E) {
    int e = blockIdx.x * 256 + threadIdx.x;
    if (e >= E) return;
    int src = ei[e];
    int dst = ei[E + e];
    int pos = atomicAdd(&cur[dst], 1);
    csr[pos] = src;
}

// ---------------------------------------------------------------------------
// EA = segment_sum(edge_attr, dst): scatter red.v4
// ---------------------------------------------------------------------------
__global__ void k_ea(const int* __restrict__ ei, const float* __restrict__ edge_attr,
                     float* __restrict__ EA, int E) {
    int idx = blockIdx.x * 256 + threadIdx.x;
    if (idx >= E * 3) return;
    int e = idx / 3;
    int j = idx - e * 3;
    int dst = ei[E + e];
    float4 v = ((const float4*)edge_attr)[e * 3 + j];
    red_add_v4(EA + dst * 12 + j * 4, v);
}

// ---------------------------------------------------------------------------
// Fused layer GEMM. Tile: 128 nodes x 128 outputs (64 t-ch | 64 pre-ch).
//   X = FIRST ? lrelu([state|action]@W_in + b_in)  (computed in-loader)
//             : h (read from global)
//   t   = X @ W_nbr
//   pre = X @ W_self + EA @ W_edge + b_conv
// 256 threads; thread (ty,tx) owns 8 nodes x 8 channels via fma.rn.f32x2.
// ---------------------------------------------------------------------------
#define OFF_X   0
#define OFF_W   8704
#define OFF_EA  16896
#define OFF_WE  18432
#define OFF_B   19200
#define OFF_WIN 19264
#define OFF_BIN 20032
#define SMEM_FLOATS 20096

template<bool FIRST>
__global__ void __launch_bounds__(256, 2)
k_gemm(const float* __restrict__ state, const float* __restrict__ action,
       const float* __restrict__ Win, const float* __restrict__ bin,
       const float* __restrict__ h, const float* __restrict__ EA,
       const float* __restrict__ Wn, const float* __restrict__ Wsf,
       const float* __restrict__ We, const float* __restrict__ bias,
       float* __restrict__ t, float* __restrict__ pre, int N) {
    extern __shared__ float sm[];
    int tid = threadIdx.x;
    int base = blockIdx.x * 128;

    // ---- phase A: stage weights / EA / (h or W_in) ----
    if (!FIRST) {
        for (int j = tid; j < 2048; j += 256) {
            int node = j >> 4, kq = j & 15;
            int gn = base + node;
            float4 v = make_float4(0.f, 0.f, 0.f, 0.f);
            if (gn < N) v = ((const float4*)h)[gn * 16 + kq];
            *(float4*)&sm[OFF_X + node * 68 + kq * 4] = v;
        }
    } else {
        for (int j = tid; j < 768; j += 256) sm[OFF_WIN + j] = Win[j];
        if (tid < 64) sm[OFF_BIN + tid] = bin[tid];
    }
    for (int j = tid; j < 2048; j += 256) {
        int k = j >> 5, c4 = j & 31;
        float4 wv = (c4 < 16) ? ((const float4*)Wn)[k * 16 + c4]
                              : ((const float4*)Wsf)[k * 16 + (c4 - 16)];
        *(float4*)&sm[OFF_W + k * 128 + c4 * 4] = wv;
    }
    for (int j = tid; j < 1536; j += 256) {
        int node = j / 12, q = j - node * 12;
        int gn = base + node;
        sm[OFF_EA + node * 12 + q] = (gn < N) ? EA[gn * 12 + q] : 0.0f;
    }
    for (int j = tid; j < 768; j += 256) sm[OFF_WE + j] = We[j];
    if (tid < 64) sm[OFF_B + tid] = bias[tid];
    __syncthreads();

    // ---- phase B (FIRST only): compute X = lrelu([s|a]@W_in + b_in) ----
    if (FIRST) {
        int node = tid & 127, half = tid >> 7;
        int gn = base + node;
        float xin[12];
#pragma unroll
        for (int k = 0; k < 12; k++) xin[k] = 0.0f;
        if (gn < N) {
#pragma unroll
            for (int k = 0; k < 8; k++) xin[k] = state[gn * 8 + k];
#pragma unroll
            for (int k = 0; k < 4; k++) xin[8 + k] = action[gn * 4 + k];
        }
        int c0 = half * 32;
#pragma unroll 8
        for (int c = c0; c < c0 + 32; c++) {
            float a = sm[OFF_BIN + c];
#pragma unroll
            for (int k = 0; k < 12; k++) a += xin[k] * sm[OFF_WIN + k * 64 + c];
            sm[OFF_X + node * 68 + c] = lrelu(a);
        }
        __syncthreads();
    }

    // ---- main GEMM ----
    int ty = tid >> 4;
    int tx = tid & 15;
    bool isPre = tx >= 8;
    int cb = (tx & 7) * 8;

    u64 acc[8][4];
    if (isPre) {
        const u64* b2 = (const u64*)&sm[OFF_B + cb];
#pragma unroll
        for (int n = 0; n < 8; n++) {
            acc[n][0] = b2[0]; acc[n][1] = b2[1];
            acc[n][2] = b2[2]; acc[n][3] = b2[3];
        }
    } else {
#pragma unroll
        for (int n = 0; n < 8; n++)
#pragma unroll
            for (int q = 0; q < 4; q++) acc[n][q] = 0ull;
    }

    const float* xrow  = &sm[OFF_X + ty * 8 * 68];
    const float* wbase = &sm[OFF_W + (isPre ? 64 : 0) + cb];

#pragma unroll 4
    for (int k = 0; k < 64; k++) {
        const ulonglong2* w2 = (const ulonglong2*)(wbase + k * 128);
        ulonglong2 wa = w2[0], wb = w2[1];
#pragma unroll
        for (int n = 0; n < 8; n++) {
            u64 a = pack2(xrow[n * 68 + k]);
            fma2(acc[n][0], a, wa.x); fma2(acc[n][1], a, wa.y);
            fma2(acc[n][2], a, wb.x); fma2(acc[n][3], a, wb.y);
        }
    }
    if (isPre) {
        const float* earow  = &sm[OFF_EA + ty * 8 * 12];
        const float* webase = &sm[OFF_WE + cb];
#pragma unroll
        for (int k = 0; k < 12; k++) {
            const ulonglong2* w2 = (const ulonglong2*)(webase + k * 64);
            ulonglong2 wa = w2[0], wb = w2[1];
#pragma unroll
            for (int n = 0; n < 8; n++) {
                u64 a = pack2(earow[n * 12 + k]);
                fma2(acc[n][0], a, wa.x); fma2(acc[n][1], a, wa.y);
                fma2(acc[n][2], a, wb.x); fma2(acc[n][3], a, wb.y);
            }
        }
    }

    float* outp = isPre ? pre : t;
#pragma unroll
    for (int n = 0; n < 8; n++) {
        int gn = base + ty * 8 + n;
        if (gn < N) {
            ulonglong2* o = (ulonglong2*)(outp + gn * 64 + cb);
            o[0] = make_ulonglong2(acc[n][0], acc[n][1]);
            o[1] = make_ulonglong2(acc[n][2], acc[n][3]);
        }
    }
}

// ---------------------------------------------------------------------------
// CSR pull with MLP=8 batching. Warp per node, lane owns 2 channels (float2).
//   s = pre[n] + sum_{src in in(n)} t[src]
//   FINAL=0: h[n] = lrelu(s)
//   FINAL=1: y = lrelu(s).W_out + b_out -> per-graph atomic sums/counts
// ---------------------------------------------------------------------------
template<bool FINAL>
__global__ void k_pull(const int* __restrict__ off, const int* __restrict__ csr,
                       const float* __restrict__ t, const float* __restrict__ pre,
                       float* __restrict__ hout, const int* __restrict__ batch,
                       const float* __restrict__ Wout, const float* __restrict__ bout,
                       float* __restrict__ sc, int N) {
    int warp = (blockIdx.x * blockDim.x + threadIdx.x) >> 5;
    int lane = threadIdx.x & 31;
    if (warp >= N) return;
    int s = off[warp], e = off[warp + 1];
    const float2* t2 = (const float2*)t;
    float2 a0 = ((const float2*)pre)[warp * 32 + lane];
    float ax = a0.x, ay = a0.y;

    for (int j = s; j < e; j += 32) {
        int cnt = min(32, e - j);
        int sv = (j + lane < e) ? csr[j + lane] : 0;
        int i = 0;
#pragma unroll 1
        for (; i + 8 <= cnt; i += 8) {
            int b0 = __shfl_sync(0xffffffffu, sv, i + 0);
            int b1 = __shfl_sync(0xffffffffu, sv, i + 1);
            int b2 = __shfl_sync(0xffffffffu, sv, i + 2);
            int b3 = __shfl_sync(0xffffffffu, sv, i + 3);
            int b4 = __shfl_sync(0xffffffffu, sv, i + 4);
            int b5 = __shfl_sync(0xffffffffu, sv, i + 5);
            int b6 = __shfl_sync(0xffffffffu, sv, i + 6);
            int b7 = __shfl_sync(0xffffffffu, sv, i + 7);
            float2 v0 = t2[b0 * 32 + lane];
            float2 v1 = t2[b1 * 32 + lane];
            float2 v2 = t2[b2 * 32 + lane];
            float2 v3 = t2[b3 * 32 + lane];
            float2 v4 = t2[b4 * 32 + lane];
            float2 v5 = t2[b5 * 32 + lane];
            float2 v6 = t2[b6 * 32 + lane];
            float2 v7 = t2[b7 * 32 + lane];
            ax += ((v0.x + v1.x) + (v2.x + v3.x)) + ((v4.x + v5.x) + (v6.x + v7.x));
            ay += ((v0.y + v1.y) + (v2.y + v3.y)) + ((v4.y + v5.y) + (v6.y + v7.y));
        }
#pragma unroll 1
        for (; i < cnt; i++) {
            int b = __shfl_sync(0xffffffffu, sv, i);
            float2 v = t2[b * 32 + lane];
            ax += v.x; ay += v.y;
        }
    }

    float h0 = lrelu(ax), h1 = lrelu(ay);
    if (!FINAL) {
        ((float2*)hout)[warp * 32 + lane] = make_float2(h0, h1);
    } else {
        float p = h0 * __ldg(&Wout[2 * lane]) + h1 * __ldg(&Wout[2 * lane + 1]);
#pragma unroll
        for (int o = 16; o > 0; o >>= 1) p += __shfl_down_sync(0xffffffffu, p, o);
        if (lane == 0) {
            int b = batch[warp];
            atomicAdd(&sc[b], p + bout[0]);
            atomicAdd(&sc[NGRAPH + b], 1.0f);
        }
    }
}

__global__ void k_final(const float* __restrict__ sc, float* __restrict__ out, int G) {
    int i = blockIdx.x * 128 + threadIdx.x;
    if (i < G) out[i] = sc[i] / fmaxf(sc[NGRAPH + i], 1.0f);
}

// ---------------------------------------------------------------------------
extern "C" void kernel_launch(void* const* d_in, const int* in_sizes, int n_in,
                              void* d_out, int out_size) {
    const float* state     = (const float*)d_in[0];
    const float* action    = (const float*)d_in[1];
    const int*   edge_idx  = (const int*)d_in[2];
    const float* edge_attr = (const float*)d_in[3];
    const int*   batch     = (const int*)d_in[4];
    const float* W_in      = (const float*)d_in[5];
    const float* b_in      = (const float*)d_in[6];
    const float* W_self    = (const float*)d_in[7];
    const float* W_nbr     = (const float*)d_in[8];
    const float* W_edge    = (const float*)d_in[9];
    const float* b_conv    = (const float*)d_in[10];
    const float* W_out     = (const float*)d_in[11];
    const float* b_out     = (const float*)d_in[12];
    float* out = (float*)d_out;

    const int N = in_sizes[0] / 8;
    const int E = in_sizes[3] / 12;
    const int G = out_size;

    float *h_p, *t_p, *pre_p, *ea_p, *sc_p;
    int *deg_p, *off_p, *cur_p, *csr_p;
    cudaGetSymbolAddress((void**)&h_p,   g_h);
    cudaGetSymbolAddress((void**)&t_p,   g_t);
    cudaGetSymbolAddress((void**)&pre_p, g_pre);
    cudaGetSymbolAddress((void**)&ea_p,  g_EA);
    cudaGetSymbolAddress((void**)&deg_p, g_deg);
    cudaGetSymbolAddress((void**)&off_p, g_off);
    cudaGetSymbolAddress((void**)&cur_p, g_cur);
    cudaGetSymbolAddress((void**)&csr_p, g_csr);
    cudaGetSymbolAddress((void**)&sc_p,  g_sc);

    const int smemBytes = SMEM_FLOATS * 4;
    cudaFuncSetAttribute(k_gemm<true>,  cudaFuncAttributeMaxDynamicSharedMemorySize, smemBytes);
    cudaFuncSetAttribute(k_gemm<false>, cudaFuncAttributeMaxDynamicSharedMemorySize, smemBytes);

    // lazily created side streams + events (host objects; no device memory)
    static cudaStream_t sA = nullptr, sB = nullptr;
    static cudaEvent_t evRoot = nullptr, evCsr = nullptr, evEa = nullptr;
    if (!sA) {
        cudaStreamCreateWithFlags(&sA, cudaStreamNonBlocking);
        cudaStreamCreateWithFlags(&sB, cudaStreamNonBlocking);
        cudaEventCreateWithFlags(&evRoot, cudaEventDisableTiming);
        cudaEventCreateWithFlags(&evCsr,  cudaEventDisableTiming);
        cudaEventCreateWithFlags(&evEa,   cudaEventDisableTiming);
    }

    const int nodeBlocks = (N + 7) / 8;
    const int gemmBlocks = (N + 127) / 128;
    const int edgeBlocks = (E + 255) / 256;

    // fork side streams off the capture (legacy) stream
    cudaEventRecord(evRoot, 0);
    cudaStreamWaitEvent(sA, evRoot, 0);
    cudaStreamWaitEvent(sB, evRoot, 0);

    // stream A: CSR build (off critical path until pull0)
    cudaMemsetAsync(deg_p, 0, (size_t)N * sizeof(int), sA);
    k_hist<<<edgeBlocks, 256, 0, sA>>>(edge_idx, deg_p, E);
    k_scan<<<1, 1024, 0, sA>>>(deg_p, off_p, cur_p, N);
    k_fill<<<edgeBlocks, 256, 0, sA>>>(edge_idx, cur_p, csr_p, E);
    cudaEventRecord(evCsr, sA);

    // stream B: EA aggregation (needed by gemm0)
    cudaMemsetAsync(ea_p, 0, (size_t)N * 12 * sizeof(float), sB);
    k_ea<<<(E * 3 + 255) / 256, 256, 0, sB>>>(edge_idx, edge_attr, ea_p, E);
    cudaEventRecord(evEa, sB);

    // main chain on capture stream
    cudaMemsetAsync(sc_p, 0, 2 * NGRAPH * sizeof(float), 0);

    cudaStreamWaitEvent(0, evEa, 0);
    k_gemm<true><<<gemmBlocks, 256, smemBytes>>>(state, action, W_in, b_in,
                                                 nullptr, ea_p,
                                                 W_nbr, W_self, W_edge, b_conv,
                                                 t_p, pre_p, N);
    cudaStreamWaitEvent(0, evCsr, 0);
    k_pull<false><<<nodeBlocks, 256>>>(off_p, csr_p, t_p, pre_p, h_p,
                                       nullptr, nullptr, nullptr, nullptr, N);

    k_gemm<false><<<gemmBlocks, 256, smemBytes>>>(nullptr, nullptr, nullptr, nullptr,
                                                  h_p, ea_p,
                                                  W_nbr + 4096, W_self + 4096,
                                                  W_edge + 768, b_conv + 64,
                                                  t_p, pre_p, N);
    k_pull<true><<<nodeBlocks, 256>>>(off_p, csr_p, t_p, pre_p, nullptr,
                                      batch, W_out, b_out, sc_p, N);

    k_final<<<(G + 127) / 128, 128>>>(sc_p, out, G);
}